// round 1
// baseline (speedup 1.0000x reference)
#include <cuda_runtime.h>

// PureCascadedBitFFN: out[elem, j] = j-th bit (LSB=0) of k, where
// k = round-half-down(distance[elem]) = ceil(distance - 0.5).
// The reference's 16-step sigmoid cascade reduces exactly to this.
//
// Layout: out is [512*4096, 16] float32, flat. One thread per float4
// (4 bits), so every warp issues contiguous 512B STG.128 bursts.

__global__ __launch_bounds__(256) void cascaded_bits_kernel(
    const float* __restrict__ dist,
    float4* __restrict__ out,
    int nquads)
{
    int q = blockIdx.x * blockDim.x + threadIdx.x;
    if (q >= nquads) return;

    int elem = q >> 2;          // which distance element
    int bit  = (q & 3) << 2;    // starting bit of this quad: 0,4,8,12

    float r = __ldg(&dist[elem]);
    // k = ceil(r - 0.5): exact round-half-down for r in [0, 65535)
    int k = (int)ceilf(r - 0.5f);

    float4 v;
    v.x = (float)((k >> (bit + 0)) & 1);
    v.y = (float)((k >> (bit + 1)) & 1);
    v.z = (float)((k >> (bit + 2)) & 1);
    v.w = (float)((k >> (bit + 3)) & 1);
    out[q] = v;
}

extern "C" void kernel_launch(void* const* d_in, const int* in_sizes, int n_in,
                              void* d_out, int out_size)
{
    const float* dist = (const float*)d_in[0];
    float4* out = (float4*)d_out;

    int n_elems = in_sizes[0];            // 512*4096
    int nquads  = n_elems * 4;            // 16 bits / 4 per float4

    int threads = 256;
    int blocks  = (nquads + threads - 1) / threads;
    cascaded_bits_kernel<<<blocks, threads>>>(dist, out, nquads);
}

// round 2
// speedup vs baseline: 1.5014x; 1.5014x over previous
#include <cuda_runtime.h>

// PureCascadedBitFFN: out[elem, j] = j-th bit (LSB=0) of
// k = ceil(distance[elem] - 0.5) (exact reduction of the sigmoid cascade).
//
// Output [512*4096, 16] f32 = 128 MB: pure store-bandwidth problem.
// Each block owns 1024 consecutive float4-quads (256 elements).
// Each thread handles 4 quads strided by 256 -> every STG.128 is a fully
// coalesced 512B warp burst; 4 independent load->store chains per thread
// for MLP; streaming stores (__stcs) keep the dead output from thrashing L2.

__global__ __launch_bounds__(256) void cascaded_bits_kernel(
    const float* __restrict__ dist,
    float4* __restrict__ out,
    int nquads)
{
    const int base = blockIdx.x * 1024 + threadIdx.x;

    int q[4];
    float r[4];
    #pragma unroll
    for (int i = 0; i < 4; i++) {
        q[i] = base + i * 256;
        r[i] = __ldg(&dist[q[i] >> 2]);   // 4 independent front-batched loads
    }

    int k[4];
    #pragma unroll
    for (int i = 0; i < 4; i++) {
        // k = ceil(r - 0.5): exact round-half-down for r in [0, 65535)
        k[i] = (int)ceilf(r[i] - 0.5f);
    }

    #pragma unroll
    for (int i = 0; i < 4; i++) {
        const int bit = (q[i] & 3) << 2;  // starting bit: 0,4,8,12
        float4 v;
        v.x = (float)((k[i] >> (bit + 0)) & 1);
        v.y = (float)((k[i] >> (bit + 1)) & 1);
        v.z = (float)((k[i] >> (bit + 2)) & 1);
        v.w = (float)((k[i] >> (bit + 3)) & 1);
        if (q[i] < nquads)
            __stcs(&out[q[i]], v);        // streaming store: evict-first in L2
    }
}

extern "C" void kernel_launch(void* const* d_in, const int* in_sizes, int n_in,
                              void* d_out, int out_size)
{
    const float* dist = (const float*)d_in[0];
    float4* out = (float4*)d_out;

    int n_elems = in_sizes[0];            // 512*4096
    int nquads  = n_elems * 4;            // 16 bits / 4 per float4

    int blocks = (nquads + 1023) / 1024;  // 1024 quads per block
    cascaded_bits_kernel<<<blocks, 256>>>(dist, out, nquads);
}

// round 3
// speedup vs baseline: 1.5035x; 1.0014x over previous
#include <cuda_runtime.h>

// PureCascadedBitFFN: out[elem, j] = j-th bit (LSB=0) of
// k = ceil(distance[elem] - 0.5) (exact reduction of the sigmoid cascade).
//
// Output [512*4096, 16] f32 = 128 MB: pure store-bandwidth problem.
// Block tile = 2048 consecutive float4-quads; 256 threads x 8 quads each,
// strided by 256 so every STG.128 is a fully coalesced 512B warp burst.
// 8 independent load->store chains per thread for MLP; streaming stores
// (__stcs) mark the dead output evict-first in L2.
//
// Shapes are fixed (512*4096 elems -> 8,388,608 quads = 4096 * 2048),
// so no bounds checks.

__global__ __launch_bounds__(256) void cascaded_bits_kernel(
    const float* __restrict__ dist,
    float4* __restrict__ out)
{
    const int base = blockIdx.x * 2048 + threadIdx.x;

    float r[8];
    #pragma unroll
    for (int i = 0; i < 8; i++) {
        // front-batched loads; lanes within a warp broadcast-share elements
        r[i] = __ldg(&dist[(base + i * 256) >> 2]);
    }

    int k[8];
    #pragma unroll
    for (int i = 0; i < 8; i++) {
        // k = ceil(r - 0.5): exact round-half-down for r in [0, 65535)
        k[i] = (int)ceilf(r[i] - 0.5f);
    }

    #pragma unroll
    for (int i = 0; i < 8; i++) {
        const int q   = base + i * 256;
        const int bit = (q & 3) << 2;     // starting bit of this quad: 0,4,8,12
        float4 v;
        v.x = (float)((k[i] >> (bit + 0)) & 1);
        v.y = (float)((k[i] >> (bit + 1)) & 1);
        v.z = (float)((k[i] >> (bit + 2)) & 1);
        v.w = (float)((k[i] >> (bit + 3)) & 1);
        __stcs(&out[q], v);               // streaming store: evict-first in L2
    }
}

extern "C" void kernel_launch(void* const* d_in, const int* in_sizes, int n_in,
                              void* d_out, int out_size)
{
    const float* dist = (const float*)d_in[0];
    float4* out = (float4*)d_out;

    int n_elems = in_sizes[0];            // 512*4096 = 2,097,152
    int nquads  = n_elems * 4;            // 8,388,608
    int blocks  = nquads / 2048;          // 4096 (exact)

    cascaded_bits_kernel<<<blocks, 256>>>(dist, out);
}